// round 5
// baseline (speedup 1.0000x reference)
#include <cuda_runtime.h>

#define NN 50000
#define EE 800000
#define DD 128
#define SLOPE 0.2f

// ---------------- device scratch (static, no allocation) ----------------
__device__ float g_xl[NN * DD];   // lin_l(x) for current layer
__device__ float g_xr[NN * DD];   // lin_r(x) for current layer
__device__ float g_h1[NN * DD];   // layer-1 output
__device__ int   g_rowptr[NN + 1];
__device__ int   g_cnt[NN];
__device__ int   g_cursor[NN];
__device__ int   g_srcs[EE];      // edge sources sorted by dst (CSR payload)
__device__ int   g_is64;          // 1 if edge_index is int64, 0 if int32

// ---------------- packed f32x2 helpers (Blackwell) ----------------
__device__ __forceinline__ unsigned long long pk2(float a, float b) {
    unsigned long long r;
    asm("mov.b64 %0, {%1, %2};" : "=l"(r) : "f"(a), "f"(b));
    return r;
}
__device__ __forceinline__ void upk2(unsigned long long v, float& a, float& b) {
    asm("mov.b64 {%0, %1}, %2;" : "=f"(a), "=f"(b) : "l"(v));
}
__device__ __forceinline__ unsigned long long ff2(unsigned long long a,
                                                  unsigned long long b,
                                                  unsigned long long c) {
    unsigned long long d;
    asm("fma.rn.f32x2 %0, %1, %2, %3;" : "=l"(d) : "l"(a), "l"(b), "l"(c));
    return d;
}

// ---------------- zero + dtype probe (merged) ----------------
__global__ void k_zero_detect(const int* __restrict__ ei32) {
    int i = blockIdx.x * blockDim.x + threadIdx.x;
    if (i < NN) g_cnt[i] = 0;
    if (blockIdx.x == 0 && threadIdx.x < 32) {
        int nz = 0;
#pragma unroll
        for (int q = 0; q < 2; q++)
            nz |= (ei32[2 * (threadIdx.x * 2 + q) + 1] != 0);
        unsigned any = __ballot_sync(0xffffffffu, nz);
        if (threadIdx.x == 0) g_is64 = (any == 0u) ? 1 : 0;
    }
}

__device__ __forceinline__ int ld_edge(const int* ei32, int elem, int is64) {
    int v;
    if (is64) {
        long long t = ((const long long*)ei32)[elem];  // single LDG.64
        v = (int)t;
    } else {
        v = ei32[elem];
    }
    v = v < 0 ? 0 : (v >= NN ? NN - 1 : v);   // clamp: never trap
    return v;
}

// ---------------- CSR build ----------------
__global__ void k_hist(const int* __restrict__ ei32) {
    int e = blockIdx.x * blockDim.x + threadIdx.x;
    int is64 = g_is64;
    if (e < EE) {
        int d = ld_edge(ei32, EE + e, is64);
        atomicAdd(&g_cnt[d], 1);
    }
}

// Thread-coarsened single-block scan.
__global__ __launch_bounds__(1024) void k_scan() {
    const int CHUNK = 49;  // 1024*49 = 50176 >= NN
    __shared__ int wsums[32];
    __shared__ int s_total;
    int tid = threadIdx.x, lane = tid & 31, wid = tid >> 5;
    int base = tid * CHUNK;

    int sum = 0;
#pragma unroll
    for (int i = 0; i < CHUNK; i++) {
        int idx = base + i;
        if (idx < NN) sum += g_cnt[idx];
    }

    int x = sum;
#pragma unroll
    for (int off = 1; off < 32; off <<= 1) {
        int t = __shfl_up_sync(0xffffffffu, x, off);
        if (lane >= off) x += t;
    }
    if (lane == 31) wsums[wid] = x;
    __syncthreads();
    if (wid == 0) {
        int y = wsums[lane];
        int z = y;
#pragma unroll
        for (int off = 1; off < 32; off <<= 1) {
            int t = __shfl_up_sync(0xffffffffu, z, off);
            if (lane >= off) z += t;
        }
        wsums[lane] = z - y;
        if (lane == 31) s_total = z;
    }
    __syncthreads();

    int run = wsums[wid] + (x - sum);
#pragma unroll
    for (int i = 0; i < CHUNK; i++) {
        int idx = base + i;
        if (idx < NN) {
            int c = g_cnt[idx];
            g_rowptr[idx] = run;
            g_cursor[idx] = run;
            run += c;
        }
    }
    if (tid == 0) g_rowptr[NN] = s_total;
}

__global__ void k_scatter(const int* __restrict__ ei32) {
    int e = blockIdx.x * blockDim.x + threadIdx.x;
    int is64 = g_is64;
    if (e < EE) {
        int d = ld_edge(ei32, EE + e, is64);
        int s = ld_edge(ei32, e, is64);
        int pos = atomicAdd(&g_cursor[d], 1);
        g_srcs[pos] = s;
    }
}

// ---------------- GEMM: writes g_xl (from W0,b0) and g_xr (from W1,b1) ----------------
__global__ __launch_bounds__(256) void k_gemm(
    const float* __restrict__ x, int x_from_h1,
    const float* __restrict__ W0, const float* __restrict__ b0,
    const float* __restrict__ W1, const float* __restrict__ b1)
{
    __shared__ float xs[32][68];   // x tile transposed [k][row], padded
    __shared__ float ws[32 * 128]; // W chunk rows k0..k0+31 (row-major)

    const float* xx = x_from_h1 ? g_h1 : x;
    const float* W  = blockIdx.y ? W1 : W0;
    const float* bb = blockIdx.y ? b1 : b0;
    float* out      = blockIdx.y ? g_xr : g_xl;

    const int row0 = blockIdx.x * 64;
    const int tid = threadIdx.x;
    const int tx = tid & 31;   // col group (4 cols)
    const int ty = tid >> 5;   // row group (8 rows)

    unsigned long long acc[8][2];
#pragma unroll
    for (int i = 0; i < 8; i++) { acc[i][0] = 0ull; acc[i][1] = 0ull; }

    for (int k0 = 0; k0 < 128; k0 += 32) {
#pragma unroll
        for (int t = 0; t < 2; t++) {
            int idx = tid * 2 + t;          // 0..511
            int r = idx >> 3;               // local row 0..63
            int kq = idx & 7;               // float4 index along k
            int gr = row0 + r;
            float4 v = make_float4(0.f, 0.f, 0.f, 0.f);
            if (gr < NN) v = *(const float4*)&xx[gr * 128 + k0 + kq * 4];
            xs[kq * 4 + 0][r] = v.x;
            xs[kq * 4 + 1][r] = v.y;
            xs[kq * 4 + 2][r] = v.z;
            xs[kq * 4 + 3][r] = v.w;
        }
#pragma unroll
        for (int q = 0; q < 4; q++) {
            int off = (tid + q * 256) * 4;
            *(float4*)&ws[off] = *(const float4*)&W[k0 * 128 + off];
        }
        __syncthreads();

#pragma unroll
        for (int k = 0; k < 32; k++) {
            float4 a0 = *(const float4*)&xs[k][ty * 8];
            float4 a1 = *(const float4*)&xs[k][ty * 8 + 4];
            ulonglong2 wv = *(const ulonglong2*)&ws[k * 128 + tx * 4];
            unsigned long long p;
            p = pk2(a0.x, a0.x); acc[0][0] = ff2(p, wv.x, acc[0][0]); acc[0][1] = ff2(p, wv.y, acc[0][1]);
            p = pk2(a0.y, a0.y); acc[1][0] = ff2(p, wv.x, acc[1][0]); acc[1][1] = ff2(p, wv.y, acc[1][1]);
            p = pk2(a0.z, a0.z); acc[2][0] = ff2(p, wv.x, acc[2][0]); acc[2][1] = ff2(p, wv.y, acc[2][1]);
            p = pk2(a0.w, a0.w); acc[3][0] = ff2(p, wv.x, acc[3][0]); acc[3][1] = ff2(p, wv.y, acc[3][1]);
            p = pk2(a1.x, a1.x); acc[4][0] = ff2(p, wv.x, acc[4][0]); acc[4][1] = ff2(p, wv.y, acc[4][1]);
            p = pk2(a1.y, a1.y); acc[5][0] = ff2(p, wv.x, acc[5][0]); acc[5][1] = ff2(p, wv.y, acc[5][1]);
            p = pk2(a1.z, a1.z); acc[6][0] = ff2(p, wv.x, acc[6][0]); acc[6][1] = ff2(p, wv.y, acc[6][1]);
            p = pk2(a1.w, a1.w); acc[7][0] = ff2(p, wv.x, acc[7][0]); acc[7][1] = ff2(p, wv.y, acc[7][1]);
        }
        __syncthreads();
    }

    float4 b4 = *(const float4*)&bb[tx * 4];
#pragma unroll
    for (int i = 0; i < 8; i++) {
        int r = row0 + ty * 8 + i;
        if (r < NN) {
            float4 o;
            upk2(acc[i][0], o.x, o.y);
            upk2(acc[i][1], o.z, o.w);
            o.x += b4.x; o.y += b4.y; o.z += b4.z; o.w += b4.w;
            *(float4*)&out[r * 128 + tx * 4] = o;
        }
    }
}

// ---------------- fused attention + aggregation (8-lane groups, 4 edges/iter) ----------------
// One warp per dst node. grp = lane/8 picks the edge within a 4-edge batch;
// gl = lane%8 picks 16 feature dims. Per iteration: 4 independent xl-row
// gathers in flight (4x MLP), 3-shuffle logit reduce, exp on 8 lanes/edge.
// Tail masked via w=0. Cross-group combine once per node at the end.
__global__ __launch_bounds__(256) void k_aggregate(
    const float* __restrict__ att, const float* __restrict__ bias,
    float* __restrict__ out, int out_to_h1)
{
    int gw = (blockIdx.x * blockDim.x + threadIdx.x) >> 5;
    int lane = threadIdx.x & 31;
    if (gw >= NN) return;

    int grp = lane >> 3;
    int gl = lane & 7;

    float* o = out_to_h1 ? g_h1 : out;

    int beg = g_rowptr[gw];
    int end = g_rowptr[gw + 1];

    const float* xrp = &g_xr[(size_t)gw * 128 + gl * 16];
    float4 xr0 = *(const float4*)&xrp[0];
    float4 xr1 = *(const float4*)&xrp[4];
    float4 xr2 = *(const float4*)&xrp[8];
    float4 xr3 = *(const float4*)&xrp[12];
    float4 at0 = *(const float4*)&att[gl * 16 + 0];
    float4 at1 = *(const float4*)&att[gl * 16 + 4];
    float4 at2 = *(const float4*)&att[gl * 16 + 8];
    float4 at3 = *(const float4*)&att[gl * 16 + 12];

    float acc[16];
#pragma unroll
    for (int i = 0; i < 16; i++) acc[i] = 0.f;
    float wsum = 0.f;

    int nIter = (end - beg + 3) >> 2;
    for (int it = 0; it < nIter; it++) {
        int j = beg + it * 4 + grp;
        bool valid = (j < end);
        int s = valid ? g_srcs[j] : 0;
        const float* xp = &g_xl[(size_t)s * 128 + gl * 16];
        float4 xv0 = *(const float4*)&xp[0];
        float4 xv1 = *(const float4*)&xp[4];
        float4 xv2 = *(const float4*)&xp[8];
        float4 xv3 = *(const float4*)&xp[12];

        float part = 0.f;
        {
            float z;
            z = xv0.x + xr0.x; z = z > 0.f ? z : SLOPE * z; part += z * at0.x;
            z = xv0.y + xr0.y; z = z > 0.f ? z : SLOPE * z; part += z * at0.y;
            z = xv0.z + xr0.z; z = z > 0.f ? z : SLOPE * z; part += z * at0.z;
            z = xv0.w + xr0.w; z = z > 0.f ? z : SLOPE * z; part += z * at0.w;
            z = xv1.x + xr1.x; z = z > 0.f ? z : SLOPE * z; part += z * at1.x;
            z = xv1.y + xr1.y; z = z > 0.f ? z : SLOPE * z; part += z * at1.y;
            z = xv1.z + xr1.z; z = z > 0.f ? z : SLOPE * z; part += z * at1.z;
            z = xv1.w + xr1.w; z = z > 0.f ? z : SLOPE * z; part += z * at1.w;
            z = xv2.x + xr2.x; z = z > 0.f ? z : SLOPE * z; part += z * at2.x;
            z = xv2.y + xr2.y; z = z > 0.f ? z : SLOPE * z; part += z * at2.y;
            z = xv2.z + xr2.z; z = z > 0.f ? z : SLOPE * z; part += z * at2.z;
            z = xv2.w + xr2.w; z = z > 0.f ? z : SLOPE * z; part += z * at2.w;
            z = xv3.x + xr3.x; z = z > 0.f ? z : SLOPE * z; part += z * at3.x;
            z = xv3.y + xr3.y; z = z > 0.f ? z : SLOPE * z; part += z * at3.y;
            z = xv3.z + xr3.z; z = z > 0.f ? z : SLOPE * z; part += z * at3.z;
            z = xv3.w + xr3.w; z = z > 0.f ? z : SLOPE * z; part += z * at3.w;
        }
        // reduce within 8-lane group (xor < 8 stays in group)
        part += __shfl_xor_sync(0xffffffffu, part, 4);
        part += __shfl_xor_sync(0xffffffffu, part, 2);
        part += __shfl_xor_sync(0xffffffffu, part, 1);

        float w = valid ? __expf(part) : 0.f;
        acc[0]  += w * xv0.x; acc[1]  += w * xv0.y; acc[2]  += w * xv0.z; acc[3]  += w * xv0.w;
        acc[4]  += w * xv1.x; acc[5]  += w * xv1.y; acc[6]  += w * xv1.z; acc[7]  += w * xv1.w;
        acc[8]  += w * xv2.x; acc[9]  += w * xv2.y; acc[10] += w * xv2.z; acc[11] += w * xv2.w;
        acc[12] += w * xv3.x; acc[13] += w * xv3.y; acc[14] += w * xv3.z; acc[15] += w * xv3.w;
        wsum += w;
    }

    // combine the 4 groups (same gl across groups holds the same dims)
#pragma unroll
    for (int k = 0; k < 16; k++) {
        acc[k] += __shfl_xor_sync(0xffffffffu, acc[k], 8);
        acc[k] += __shfl_xor_sync(0xffffffffu, acc[k], 16);
    }
    wsum += __shfl_xor_sync(0xffffffffu, wsum, 8);
    wsum += __shfl_xor_sync(0xffffffffu, wsum, 16);

    if (grp == 0) {
        float inv = 1.f / fmaxf(wsum, 1e-16f);
        float* op = &o[(size_t)gw * 128 + gl * 16];
#pragma unroll
        for (int q = 0; q < 4; q++) {
            float4 b4 = *(const float4*)&bias[gl * 16 + q * 4];
            float4 r;
            r.x = fmaxf(acc[q * 4 + 0] * inv + b4.x, 0.f);
            r.y = fmaxf(acc[q * 4 + 1] * inv + b4.y, 0.f);
            r.z = fmaxf(acc[q * 4 + 2] * inv + b4.z, 0.f);
            r.w = fmaxf(acc[q * 4 + 3] * inv + b4.w, 0.f);
            *(float4*)&op[q * 4] = r;
        }
    }
}

// ---------------- launch ----------------
extern "C" void kernel_launch(void* const* d_in, const int* in_sizes, int n_in,
                              void* d_out, int out_size) {
    const float* x0    = (const float*)d_in[0];
    const int*   ei32  = (const int*)d_in[1];
    const float* Wl1   = (const float*)d_in[2];
    const float* bl1   = (const float*)d_in[3];
    const float* Wr1   = (const float*)d_in[4];
    const float* br1   = (const float*)d_in[5];
    const float* att1  = (const float*)d_in[6];
    const float* bias1 = (const float*)d_in[7];
    const float* Wl2   = (const float*)d_in[8];
    const float* bl2   = (const float*)d_in[9];
    const float* Wr2   = (const float*)d_in[10];
    const float* br2   = (const float*)d_in[11];
    const float* att2  = (const float*)d_in[12];
    const float* bias2 = (const float*)d_in[13];
    float* out = (float*)d_out;

    dim3 ggrid((NN + 63) / 64, 2);

    // CSR build + layer-1 gemm interleaved (gemm independent of CSR);
    // gemm1 lands at profiled launch slot (index 3).
    k_zero_detect<<<(NN + 255) / 256, 256>>>(ei32);
    k_hist<<<(EE + 255) / 256, 256>>>(ei32);
    k_scan<<<1, 1024>>>();
    k_gemm<<<ggrid, 256>>>(x0, 0, Wl1, bl1, Wr1, br1);
    k_scatter<<<(EE + 255) / 256, 256>>>(ei32);

    // layer 1 aggregate
    k_aggregate<<<(NN * 32 + 255) / 256, 256>>>(att1, bias1, out, 1);

    // layer 2
    k_gemm<<<ggrid, 256>>>(x0, 1, Wl2, bl2, Wr2, br2);
    k_aggregate<<<(NN * 32 + 255) / 256, 256>>>(att2, bias2, out, 0);
}

// round 6
// speedup vs baseline: 1.4546x; 1.4546x over previous
#include <cuda_runtime.h>

#define NN 50000
#define EE 800000
#define DD 128
#define SLOPE 0.2f

// ---------------- device scratch (static, no allocation) ----------------
__device__ float g_xl[NN * DD];
__device__ float g_xr[NN * DD];
__device__ float g_h1[NN * DD];
__device__ int   g_rowptr[NN + 1];
__device__ int   g_cnt[NN];
__device__ int   g_cursor[NN];
__device__ int   g_srcs[EE];
__device__ int   g_is64;

// ---------------- zero + dtype probe (merged) ----------------
__global__ void k_zero_detect(const int* __restrict__ ei32) {
    int i = blockIdx.x * blockDim.x + threadIdx.x;
    if (i < NN) g_cnt[i] = 0;
    if (blockIdx.x == 0 && threadIdx.x < 32) {
        int nz = 0;
#pragma unroll
        for (int q = 0; q < 2; q++)
            nz |= (ei32[2 * (threadIdx.x * 2 + q) + 1] != 0);
        unsigned any = __ballot_sync(0xffffffffu, nz);
        if (threadIdx.x == 0) g_is64 = (any == 0u) ? 1 : 0;
    }
}

__device__ __forceinline__ int ld_edge(const int* ei32, int elem, int is64) {
    int v;
    if (is64) {
        long long t = ((const long long*)ei32)[elem];
        v = (int)t;
    } else {
        v = ei32[elem];
    }
    v = v < 0 ? 0 : (v >= NN ? NN - 1 : v);
    return v;
}

// ---------------- CSR build ----------------
__global__ void k_hist(const int* __restrict__ ei32) {
    int e = blockIdx.x * blockDim.x + threadIdx.x;
    int is64 = g_is64;
    if (e < EE) {
        int d = ld_edge(ei32, EE + e, is64);
        atomicAdd(&g_cnt[d], 1);
    }
}

__global__ __launch_bounds__(1024) void k_scan() {
    const int CHUNK = 49;
    __shared__ int wsums[32];
    __shared__ int s_total;
    int tid = threadIdx.x, lane = tid & 31, wid = tid >> 5;
    int base = tid * CHUNK;

    int sum = 0;
#pragma unroll
    for (int i = 0; i < CHUNK; i++) {
        int idx = base + i;
        if (idx < NN) sum += g_cnt[idx];
    }

    int x = sum;
#pragma unroll
    for (int off = 1; off < 32; off <<= 1) {
        int t = __shfl_up_sync(0xffffffffu, x, off);
        if (lane >= off) x += t;
    }
    if (lane == 31) wsums[wid] = x;
    __syncthreads();
    if (wid == 0) {
        int y = wsums[lane];
        int z = y;
#pragma unroll
        for (int off = 1; off < 32; off <<= 1) {
            int t = __shfl_up_sync(0xffffffffu, z, off);
            if (lane >= off) z += t;
        }
        wsums[lane] = z - y;
        if (lane == 31) s_total = z;
    }
    __syncthreads();

    int run = wsums[wid] + (x - sum);
#pragma unroll
    for (int i = 0; i < CHUNK; i++) {
        int idx = base + i;
        if (idx < NN) {
            int c = g_cnt[idx];
            g_rowptr[idx] = run;
            g_cursor[idx] = run;
            run += c;
        }
    }
    if (tid == 0) g_rowptr[NN] = s_total;
}

__global__ void k_scatter(const int* __restrict__ ei32) {
    int e = blockIdx.x * blockDim.x + threadIdx.x;
    int is64 = g_is64;
    if (e < EE) {
        int d = ld_edge(ei32, EE + e, is64);
        int s = ld_edge(ei32, e, is64);
        int pos = atomicAdd(&g_cursor[d], 1);
        g_srcs[pos] = s;
    }
}

// ---------------- tf32 tensor-core GEMM ----------------
// out[r][n] = sum_k x[r][k] * W[k][n] + b[n],  M=NN rows, N=K=128.
// Block tile 128x128, BK=32, 8 warps: mwarp=wid&3 (m32), nwarp=wid>>2 (n64).
// mma.sync.m16n8k8 tf32, fp32 accumulate. cvt.rna for operand rounding.
// xs swizzle: word(m,k) = m*32 + (((k>>2)+m)&7)*4 + (k&3)  -> A frag LDS conflict-free.
// ws padded stride 136 -> B frag LDS conflict-free.
__device__ __forceinline__ unsigned tf32cvt(float f) {
    unsigned r;
    asm("cvt.rna.tf32.f32 %0, %1;" : "=r"(r) : "f"(f));
    return r;
}

__global__ __launch_bounds__(256) void k_gemm(
    const float* __restrict__ x, int x_from_h1,
    const float* __restrict__ W0, const float* __restrict__ b0,
    const float* __restrict__ W1, const float* __restrict__ b1)
{
    __shared__ float xs[128 * 32];   // swizzled
    __shared__ float ws[32 * 136];   // padded row stride 136

    const float* xx = x_from_h1 ? g_h1 : x;
    const float* W  = blockIdx.y ? W1 : W0;
    const float* bb = blockIdx.y ? b1 : b0;
    float* out      = blockIdx.y ? g_xr : g_xl;

    const int row0 = blockIdx.x * 128;
    const int tid = threadIdx.x;
    const int wid = tid >> 5;
    const int lane = tid & 31;
    const int g = lane >> 2;      // group id 0..7
    const int t = lane & 3;       // thread-in-group 0..3

    const int mwarp = wid & 3;    // 0..3 -> 32 rows each
    const int nwarp = wid >> 2;   // 0..1 -> 64 cols each

    float acc[2][8][4];
#pragma unroll
    for (int mt = 0; mt < 2; mt++)
#pragma unroll
        for (int nt = 0; nt < 8; nt++)
#pragma unroll
            for (int c = 0; c < 4; c++) acc[mt][nt][c] = 0.f;

    for (int kc = 0; kc < 128; kc += 32) {
        // load x tile (128 rows x 32 k) into swizzled xs
#pragma unroll
        for (int it = 0; it < 4; it++) {
            int idx = tid + it * 256;      // 0..1023
            int m = idx >> 3;              // 0..127
            int kq = idx & 7;              // float4 group along k
            int gr = row0 + m;
            float4 v = make_float4(0.f, 0.f, 0.f, 0.f);
            if (gr < NN) v = *(const float4*)&xx[gr * 128 + kc + kq * 4];
            *(float4*)&xs[m * 32 + (((kq + m) & 7) << 2)] = v;
        }
        // load W chunk (32 k x 128 n) into padded ws
#pragma unroll
        for (int it = 0; it < 4; it++) {
            int idx = tid + it * 256;
            int k = idx >> 5;              // 0..31
            int nq = idx & 31;             // float4 group along n
            float4 v = *(const float4*)&W[(kc + k) * 128 + nq * 4];
            *(float4*)&ws[k * 136 + nq * 4] = v;
        }
        __syncthreads();

#pragma unroll
        for (int k8 = 0; k8 < 4; k8++) {
            int kb = k8 * 8;
            // A fragments for 2 m-tiles
            unsigned af[2][4];
#pragma unroll
            for (int mt = 0; mt < 2; mt++) {
                int m0 = mwarp * 32 + mt * 16 + g;
                int m1 = m0 + 8;
                int klo = kb + t, khi = kb + t + 4;
                af[mt][0] = tf32cvt(xs[m0 * 32 + ((((klo >> 2) + m0) & 7) << 2) + (klo & 3)]);
                af[mt][1] = tf32cvt(xs[m1 * 32 + ((((klo >> 2) + m1) & 7) << 2) + (klo & 3)]);
                af[mt][2] = tf32cvt(xs[m0 * 32 + ((((khi >> 2) + m0) & 7) << 2) + (khi & 3)]);
                af[mt][3] = tf32cvt(xs[m1 * 32 + ((((khi >> 2) + m1) & 7) << 2) + (khi & 3)]);
            }
            // B fragments for 8 n-tiles
            unsigned bf[8][2];
#pragma unroll
            for (int nt = 0; nt < 8; nt++) {
                int n = nwarp * 64 + nt * 8 + g;
                bf[nt][0] = tf32cvt(ws[(kb + t) * 136 + n]);
                bf[nt][1] = tf32cvt(ws[(kb + t + 4) * 136 + n]);
            }
#pragma unroll
            for (int mt = 0; mt < 2; mt++)
#pragma unroll
                for (int nt = 0; nt < 8; nt++) {
                    asm volatile(
                        "mma.sync.aligned.m16n8k8.row.col.f32.tf32.tf32.f32 "
                        "{%0,%1,%2,%3}, {%4,%5,%6,%7}, {%8,%9}, {%0,%1,%2,%3};"
                        : "+f"(acc[mt][nt][0]), "+f"(acc[mt][nt][1]),
                          "+f"(acc[mt][nt][2]), "+f"(acc[mt][nt][3])
                        : "r"(af[mt][0]), "r"(af[mt][1]), "r"(af[mt][2]), "r"(af[mt][3]),
                          "r"(bf[nt][0]), "r"(bf[nt][1]));
                }
        }
        __syncthreads();
    }

    // epilogue: c0,c1 -> (row, col..col+1); c2,c3 -> (row+8, col..col+1)
#pragma unroll
    for (int mt = 0; mt < 2; mt++) {
#pragma unroll
        for (int nt = 0; nt < 8; nt++) {
            int col = nwarp * 64 + nt * 8 + 2 * t;
            float bx = bb[col], by = bb[col + 1];
            int r0 = row0 + mwarp * 32 + mt * 16 + g;
            int r1 = r0 + 8;
            if (r0 < NN) {
                float2 v = make_float2(acc[mt][nt][0] + bx, acc[mt][nt][1] + by);
                *(float2*)&out[r0 * 128 + col] = v;
            }
            if (r1 < NN) {
                float2 v = make_float2(acc[mt][nt][2] + bx, acc[mt][nt][3] + by);
                *(float2*)&out[r1 * 128 + col] = v;
            }
        }
    }
}

// ---------------- fused attention + aggregation (R2 measured-good form) ----------------
__global__ __launch_bounds__(256) void k_aggregate(
    const float* __restrict__ att, const float* __restrict__ bias,
    float* __restrict__ out, int out_to_h1)
{
    int gw = (blockIdx.x * blockDim.x + threadIdx.x) >> 5;
    int lane = threadIdx.x & 31;
    if (gw >= NN) return;

    float* o = out_to_h1 ? g_h1 : out;

    int beg = g_rowptr[gw];
    int end = g_rowptr[gw + 1];

    float4 xrv = *(const float4*)&g_xr[(size_t)gw * 128 + lane * 4];
    float4 at4 = *(const float4*)&att[lane * 4];

    float4 acc = make_float4(0.f, 0.f, 0.f, 0.f);
    float wsum = 0.f;

    int sA = (beg < end) ? g_srcs[beg] : 0;
    for (int j = beg; j < end; j++) {
        int s = sA;
        if (j + 1 < end) sA = g_srcs[j + 1];
        float4 xv = *(const float4*)&g_xl[(size_t)s * 128 + lane * 4];

        float z0 = xv.x + xrv.x; z0 = z0 > 0.f ? z0 : SLOPE * z0;
        float z1 = xv.y + xrv.y; z1 = z1 > 0.f ? z1 : SLOPE * z1;
        float z2 = xv.z + xrv.z; z2 = z2 > 0.f ? z2 : SLOPE * z2;
        float z3 = xv.w + xrv.w; z3 = z3 > 0.f ? z3 : SLOPE * z3;
        float part = z0 * at4.x + z1 * at4.y + z2 * at4.z + z3 * at4.w;

        part += __shfl_xor_sync(0xffffffffu, part, 16);
        part += __shfl_xor_sync(0xffffffffu, part, 8);
        part += __shfl_xor_sync(0xffffffffu, part, 4);
        part += __shfl_xor_sync(0xffffffffu, part, 2);
        part += __shfl_xor_sync(0xffffffffu, part, 1);

        float w = __expf(part);
        acc.x += w * xv.x;
        acc.y += w * xv.y;
        acc.z += w * xv.z;
        acc.w += w * xv.w;
        wsum += w;
    }

    float inv = 1.f / fmaxf(wsum, 1e-16f);
    float4 b4 = *(const float4*)&bias[lane * 4];
    float4 r;
    r.x = fmaxf(acc.x * inv + b4.x, 0.f);
    r.y = fmaxf(acc.y * inv + b4.y, 0.f);
    r.z = fmaxf(acc.z * inv + b4.z, 0.f);
    r.w = fmaxf(acc.w * inv + b4.w, 0.f);
    *(float4*)&o[(size_t)gw * 128 + lane * 4] = r;
}

// ---------------- launch ----------------
extern "C" void kernel_launch(void* const* d_in, const int* in_sizes, int n_in,
                              void* d_out, int out_size) {
    const float* x0    = (const float*)d_in[0];
    const int*   ei32  = (const int*)d_in[1];
    const float* Wl1   = (const float*)d_in[2];
    const float* bl1   = (const float*)d_in[3];
    const float* Wr1   = (const float*)d_in[4];
    const float* br1   = (const float*)d_in[5];
    const float* att1  = (const float*)d_in[6];
    const float* bias1 = (const float*)d_in[7];
    const float* Wl2   = (const float*)d_in[8];
    const float* bl2   = (const float*)d_in[9];
    const float* Wr2   = (const float*)d_in[10];
    const float* br2   = (const float*)d_in[11];
    const float* att2  = (const float*)d_in[12];
    const float* bias2 = (const float*)d_in[13];
    float* out = (float*)d_out;

    dim3 ggrid((NN + 127) / 128, 2);

    // CSR build + layer-1 gemm interleaved; gemm1 at profiled slot (index 3).
    k_zero_detect<<<(NN + 255) / 256, 256>>>(ei32);
    k_hist<<<(EE + 255) / 256, 256>>>(ei32);
    k_scan<<<1, 1024>>>();
    k_gemm<<<ggrid, 256>>>(x0, 0, Wl1, bl1, Wr1, br1);
    k_scatter<<<(EE + 255) / 256, 256>>>(ei32);

    k_aggregate<<<(NN * 32 + 255) / 256, 256>>>(att1, bias1, out, 1);

    k_gemm<<<ggrid, 256>>>(x0, 1, Wl2, bl2, Wr2, br2);
    k_aggregate<<<(NN * 32 + 255) / 256, 256>>>(att2, bias2, out, 0);
}

// round 7
// speedup vs baseline: 1.5486x; 1.0646x over previous
#include <cuda_runtime.h>

#define NN 50000
#define EE 800000
#define DD 128
#define SLOPE 0.2f

// ---------------- device scratch (static, no allocation) ----------------
__device__ float g_xl[NN * DD];
__device__ float g_xr[NN * DD];
__device__ float g_h1[NN * DD];
__device__ int   g_rowptr[NN + 1];
__device__ int   g_cnt[NN];
__device__ int   g_cursor[NN];
__device__ int   g_srcs[EE];
__device__ int   g_is64;

// ---------------- zero + dtype probe (merged) ----------------
__global__ void k_zero_detect(const int* __restrict__ ei32) {
    int i = blockIdx.x * blockDim.x + threadIdx.x;
    if (i < NN) g_cnt[i] = 0;
    if (blockIdx.x == 0 && threadIdx.x < 32) {
        int nz = 0;
#pragma unroll
        for (int q = 0; q < 2; q++)
            nz |= (ei32[2 * (threadIdx.x * 2 + q) + 1] != 0);
        unsigned any = __ballot_sync(0xffffffffu, nz);
        if (threadIdx.x == 0) g_is64 = (any == 0u) ? 1 : 0;
    }
}

__device__ __forceinline__ int ld_edge(const int* ei32, int elem, int is64) {
    int v;
    if (is64) {
        long long t = ((const long long*)ei32)[elem];
        v = (int)t;
    } else {
        v = ei32[elem];
    }
    v = v < 0 ? 0 : (v >= NN ? NN - 1 : v);
    return v;
}

// ---------------- CSR build ----------------
__global__ void k_hist(const int* __restrict__ ei32) {
    int e = blockIdx.x * blockDim.x + threadIdx.x;
    int is64 = g_is64;
    if (e < EE) {
        int d = ld_edge(ei32, EE + e, is64);
        atomicAdd(&g_cnt[d], 1);
    }
}

__global__ __launch_bounds__(1024) void k_scan() {
    const int CHUNK = 49;
    __shared__ int wsums[32];
    __shared__ int s_total;
    int tid = threadIdx.x, lane = tid & 31, wid = tid >> 5;
    int base = tid * CHUNK;

    int sum = 0;
#pragma unroll
    for (int i = 0; i < CHUNK; i++) {
        int idx = base + i;
        if (idx < NN) sum += g_cnt[idx];
    }

    int x = sum;
#pragma unroll
    for (int off = 1; off < 32; off <<= 1) {
        int t = __shfl_up_sync(0xffffffffu, x, off);
        if (lane >= off) x += t;
    }
    if (lane == 31) wsums[wid] = x;
    __syncthreads();
    if (wid == 0) {
        int y = wsums[lane];
        int z = y;
#pragma unroll
        for (int off = 1; off < 32; off <<= 1) {
            int t = __shfl_up_sync(0xffffffffu, z, off);
            if (lane >= off) z += t;
        }
        wsums[lane] = z - y;
        if (lane == 31) s_total = z;
    }
    __syncthreads();

    int run = wsums[wid] + (x - sum);
#pragma unroll
    for (int i = 0; i < CHUNK; i++) {
        int idx = base + i;
        if (idx < NN) {
            int c = g_cnt[idx];
            g_rowptr[idx] = run;
            g_cursor[idx] = run;
            run += c;
        }
    }
    if (tid == 0) g_rowptr[NN] = s_total;
}

__global__ void k_scatter(const int* __restrict__ ei32) {
    int e = blockIdx.x * blockDim.x + threadIdx.x;
    int is64 = g_is64;
    if (e < EE) {
        int d = ld_edge(ei32, EE + e, is64);
        int s = ld_edge(ei32, e, is64);
        int pos = atomicAdd(&g_cursor[d], 1);
        g_srcs[pos] = s;
    }
}

// ---------------- tf32 tensor-core GEMM (cp.async double-buffered) ----------------
__device__ __forceinline__ unsigned tf32cvt(float f) {
    unsigned r;
    asm("cvt.rna.tf32.f32 %0, %1;" : "=r"(r) : "f"(f));
    return r;
}

__device__ __forceinline__ void cpasync16(unsigned dst_smem, const void* src, int sz) {
    asm volatile("cp.async.ca.shared.global [%0], [%1], 16, %2;"
                 :: "r"(dst_smem), "l"(src), "r"(sz));
}

__global__ __launch_bounds__(256) void k_gemm(
    const float* __restrict__ x, int x_from_h1,
    const float* __restrict__ W0, const float* __restrict__ b0,
    const float* __restrict__ W1, const float* __restrict__ b1)
{
    __shared__ float xs[2][128 * 32];   // swizzled A tiles
    __shared__ float ws[2][32 * 136];   // padded-stride W chunks

    const float* xx = x_from_h1 ? g_h1 : x;
    const float* W  = blockIdx.y ? W1 : W0;
    const float* bb = blockIdx.y ? b1 : b0;
    float* out      = blockIdx.y ? g_xr : g_xl;

    const int row0 = blockIdx.x * 128;
    const int tid = threadIdx.x;
    const int wid = tid >> 5;
    const int lane = tid & 31;
    const int g = lane >> 2;
    const int t = lane & 3;

    const int mwarp = wid & 3;    // 0..3 -> 32 rows each
    const int nwarp = wid >> 2;   // 0..1 -> 64 cols each

    float acc[2][8][4];
#pragma unroll
    for (int mt = 0; mt < 2; mt++)
#pragma unroll
        for (int nt = 0; nt < 8; nt++)
#pragma unroll
            for (int c = 0; c < 4; c++) acc[mt][nt][c] = 0.f;

    // async chunk loader: A tile (128x32) + W chunk (32x128) into buffer buf
    auto load_chunk = [&](int kc, int buf) {
#pragma unroll
        for (int it = 0; it < 4; it++) {
            int idx = tid + it * 256;      // 0..1023
            int m = idx >> 3;
            int kq = idx & 7;
            int gr = row0 + m;
            unsigned dst = (unsigned)__cvta_generic_to_shared(
                &xs[buf][m * 32 + (((kq + m) & 7) << 2)]);
            const float* src = &xx[(size_t)(gr < NN ? gr : 0) * 128 + kc + kq * 4];
            cpasync16(dst, src, gr < NN ? 16 : 0);
        }
#pragma unroll
        for (int it = 0; it < 4; it++) {
            int idx = tid + it * 256;
            int k = idx >> 5;
            int nq = idx & 31;
            unsigned dst = (unsigned)__cvta_generic_to_shared(&ws[buf][k * 136 + nq * 4]);
            cpasync16(dst, &W[(kc + k) * 128 + nq * 4], 16);
        }
        asm volatile("cp.async.commit_group;");
    };

    load_chunk(0, 0);

#pragma unroll
    for (int c = 0; c < 4; c++) {
        int buf = c & 1;
        if (c < 3) {
            load_chunk((c + 1) * 32, buf ^ 1);
            asm volatile("cp.async.wait_group 1;");
        } else {
            asm volatile("cp.async.wait_group 0;");
        }
        __syncthreads();

        const float* xsb = xs[buf];
        const float* wsb = ws[buf];
#pragma unroll
        for (int k8 = 0; k8 < 4; k8++) {
            int kb = k8 * 8;
            unsigned af[2][4];
#pragma unroll
            for (int mt = 0; mt < 2; mt++) {
                int m0 = mwarp * 32 + mt * 16 + g;
                int m1 = m0 + 8;
                int klo = kb + t, khi = kb + t + 4;
                af[mt][0] = tf32cvt(xsb[m0 * 32 + ((((klo >> 2) + m0) & 7) << 2) + (klo & 3)]);
                af[mt][1] = tf32cvt(xsb[m1 * 32 + ((((klo >> 2) + m1) & 7) << 2) + (klo & 3)]);
                af[mt][2] = tf32cvt(xsb[m0 * 32 + ((((khi >> 2) + m0) & 7) << 2) + (khi & 3)]);
                af[mt][3] = tf32cvt(xsb[m1 * 32 + ((((khi >> 2) + m1) & 7) << 2) + (khi & 3)]);
            }
            unsigned bf[8][2];
#pragma unroll
            for (int nt = 0; nt < 8; nt++) {
                int n = nwarp * 64 + nt * 8 + g;
                bf[nt][0] = tf32cvt(wsb[(kb + t) * 136 + n]);
                bf[nt][1] = tf32cvt(wsb[(kb + t + 4) * 136 + n]);
            }
#pragma unroll
            for (int mt = 0; mt < 2; mt++)
#pragma unroll
                for (int nt = 0; nt < 8; nt++) {
                    asm volatile(
                        "mma.sync.aligned.m16n8k8.row.col.f32.tf32.tf32.f32 "
                        "{%0,%1,%2,%3}, {%4,%5,%6,%7}, {%8,%9}, {%0,%1,%2,%3};"
                        : "+f"(acc[mt][nt][0]), "+f"(acc[mt][nt][1]),
                          "+f"(acc[mt][nt][2]), "+f"(acc[mt][nt][3])
                        : "r"(af[mt][0]), "r"(af[mt][1]), "r"(af[mt][2]), "r"(af[mt][3]),
                          "r"(bf[nt][0]), "r"(bf[nt][1]));
                }
        }
        __syncthreads();
    }

#pragma unroll
    for (int mt = 0; mt < 2; mt++) {
#pragma unroll
        for (int nt = 0; nt < 8; nt++) {
            int col = nwarp * 64 + nt * 8 + 2 * t;
            float bx = bb[col], by = bb[col + 1];
            int r0 = row0 + mwarp * 32 + mt * 16 + g;
            int r1 = r0 + 8;
            if (r0 < NN) {
                float2 v = make_float2(acc[mt][nt][0] + bx, acc[mt][nt][1] + by);
                *(float2*)&out[r0 * 128 + col] = v;
            }
            if (r1 < NN) {
                float2 v = make_float2(acc[mt][nt][2] + bx, acc[mt][nt][3] + by);
                *(float2*)&out[r1 * 128 + col] = v;
            }
        }
    }
}

// ---------------- fused attention + aggregation (depth-2 pipelined gather) ----------------
// One warp per dst node. Edge j's xl row is loaded one iteration early; its
// src index two iterations early — the srcs->xl chain never sits on the
// critical path of the compute loop.
__global__ __launch_bounds__(256) void k_aggregate(
    const float* __restrict__ att, const float* __restrict__ bias,
    float* __restrict__ out, int out_to_h1)
{
    int gw = (blockIdx.x * blockDim.x + threadIdx.x) >> 5;
    int lane = threadIdx.x & 31;
    if (gw >= NN) return;

    float* o = out_to_h1 ? g_h1 : out;

    int beg = g_rowptr[gw];
    int end = g_rowptr[gw + 1];

    float4 xrv = *(const float4*)&g_xr[(size_t)gw * 128 + lane * 4];
    float4 at4 = *(const float4*)&att[lane * 4];

    float4 acc = make_float4(0.f, 0.f, 0.f, 0.f);
    float wsum = 0.f;

    int s_nxt = (beg + 1 < end) ? g_srcs[beg + 1] : 0;
    float4 xv_cur;
    if (beg < end) {
        int s0 = g_srcs[beg];
        xv_cur = *(const float4*)&g_xl[(size_t)s0 * 128 + lane * 4];
    }

    for (int j = beg; j < end; j++) {
        // prefetch: src index for j+2, xl row for j+1 (both issued before compute)
        int s_nn = (j + 2 < end) ? g_srcs[j + 2] : 0;
        float4 xv_nxt;
        if (j + 1 < end)
            xv_nxt = *(const float4*)&g_xl[(size_t)s_nxt * 128 + lane * 4];

        float z0 = xv_cur.x + xrv.x; z0 = z0 > 0.f ? z0 : SLOPE * z0;
        float z1 = xv_cur.y + xrv.y; z1 = z1 > 0.f ? z1 : SLOPE * z1;
        float z2 = xv_cur.z + xrv.z; z2 = z2 > 0.f ? z2 : SLOPE * z2;
        float z3 = xv_cur.w + xrv.w; z3 = z3 > 0.f ? z3 : SLOPE * z3;
        float part = z0 * at4.x + z1 * at4.y + z2 * at4.z + z3 * at4.w;

        part += __shfl_xor_sync(0xffffffffu, part, 16);
        part += __shfl_xor_sync(0xffffffffu, part, 8);
        part += __shfl_xor_sync(0xffffffffu, part, 4);
        part += __shfl_xor_sync(0xffffffffu, part, 2);
        part += __shfl_xor_sync(0xffffffffu, part, 1);

        float w = __expf(part);
        acc.x += w * xv_cur.x;
        acc.y += w * xv_cur.y;
        acc.z += w * xv_cur.z;
        acc.w += w * xv_cur.w;
        wsum += w;

        xv_cur = xv_nxt;
        s_nxt = s_nn;
    }

    float inv = 1.f / fmaxf(wsum, 1e-16f);
    float4 b4 = *(const float4*)&bias[lane * 4];
    float4 r;
    r.x = fmaxf(acc.x * inv + b4.x, 0.f);
    r.y = fmaxf(acc.y * inv + b4.y, 0.f);
    r.z = fmaxf(acc.z * inv + b4.z, 0.f);
    r.w = fmaxf(acc.w * inv + b4.w, 0.f);
    *(float4*)&o[(size_t)gw * 128 + lane * 4] = r;
}

// ---------------- launch ----------------
extern "C" void kernel_launch(void* const* d_in, const int* in_sizes, int n_in,
                              void* d_out, int out_size) {
    const float* x0    = (const float*)d_in[0];
    const int*   ei32  = (const int*)d_in[1];
    const float* Wl1   = (const float*)d_in[2];
    const float* bl1   = (const float*)d_in[3];
    const float* Wr1   = (const float*)d_in[4];
    const float* br1   = (const float*)d_in[5];
    const float* att1  = (const float*)d_in[6];
    const float* bias1 = (const float*)d_in[7];
    const float* Wl2   = (const float*)d_in[8];
    const float* bl2   = (const float*)d_in[9];
    const float* Wr2   = (const float*)d_in[10];
    const float* br2   = (const float*)d_in[11];
    const float* att2  = (const float*)d_in[12];
    const float* bias2 = (const float*)d_in[13];
    float* out = (float*)d_out;

    dim3 ggrid((NN + 127) / 128, 2);

    // CSR build + layer-1 gemm interleaved; gemm1 at profiled slot (index 3).
    k_zero_detect<<<(NN + 255) / 256, 256>>>(ei32);
    k_hist<<<(EE + 255) / 256, 256>>>(ei32);
    k_scan<<<1, 1024>>>();
    k_gemm<<<ggrid, 256>>>(x0, 0, Wl1, bl1, Wr1, br1);
    k_scatter<<<(EE + 255) / 256, 256>>>(ei32);

    k_aggregate<<<(NN * 32 + 255) / 256, 256>>>(att1, bias1, out, 1);

    k_gemm<<<ggrid, 256>>>(x0, 1, Wl2, bl2, Wr2, br2);
    k_aggregate<<<(NN * 32 + 255) / 256, 256>>>(att2, bias2, out, 0);
}

// round 12
// speedup vs baseline: 1.5686x; 1.0129x over previous
#include <cuda_runtime.h>

#define NN 50000
#define EE 800000
#define DD 128
#define SLOPE 0.2f

// ---------------- device scratch (static, no allocation) ----------------
__device__ float g_xl[NN * DD];
__device__ float g_xr[NN * DD];
__device__ float g_h1[NN * DD];
__device__ int   g_rowptr[NN + 1];
__device__ int   g_cnt[NN];
__device__ int   g_cursor[NN];
__device__ int   g_srcs[EE];
__device__ int   g_is64;

// ---------------- zero + dtype probe (merged) ----------------
__global__ void k_zero_detect(const int* __restrict__ ei32) {
    int i = blockIdx.x * blockDim.x + threadIdx.x;
    if (i < NN) g_cnt[i] = 0;
    if (blockIdx.x == 0 && threadIdx.x < 32) {
        int nz = 0;
#pragma unroll
        for (int q = 0; q < 2; q++)
            nz |= (ei32[2 * (threadIdx.x * 2 + q) + 1] != 0);
        unsigned any = __ballot_sync(0xffffffffu, nz);
        if (threadIdx.x == 0) g_is64 = (any == 0u) ? 1 : 0;
    }
}

__device__ __forceinline__ int ld_edge(const int* ei32, int elem, int is64) {
    int v;
    if (is64) {
        long long t = ((const long long*)ei32)[elem];
        v = (int)t;
    } else {
        v = ei32[elem];
    }
    v = v < 0 ? 0 : (v >= NN ? NN - 1 : v);
    return v;
}

// ---------------- CSR build ----------------
__global__ void k_hist(const int* __restrict__ ei32) {
    int e = blockIdx.x * blockDim.x + threadIdx.x;
    int is64 = g_is64;
    if (e < EE) {
        int d = ld_edge(ei32, EE + e, is64);
        atomicAdd(&g_cnt[d], 1);
    }
}

__global__ __launch_bounds__(1024) void k_scan() {
    const int CHUNK = 49;
    __shared__ int wsums[32];
    __shared__ int s_total;
    int tid = threadIdx.x, lane = tid & 31, wid = tid >> 5;
    int base = tid * CHUNK;

    int sum = 0;
#pragma unroll
    for (int i = 0; i < CHUNK; i++) {
        int idx = base + i;
        if (idx < NN) sum += g_cnt[idx];
    }

    int x = sum;
#pragma unroll
    for (int off = 1; off < 32; off <<= 1) {
        int t = __shfl_up_sync(0xffffffffu, x, off);
        if (lane >= off) x += t;
    }
    if (lane == 31) wsums[wid] = x;
    __syncthreads();
    if (wid == 0) {
        int y = wsums[lane];
        int z = y;
#pragma unroll
        for (int off = 1; off < 32; off <<= 1) {
            int t = __shfl_up_sync(0xffffffffu, z, off);
            if (lane >= off) z += t;
        }
        wsums[lane] = z - y;
        if (lane == 31) s_total = z;
    }
    __syncthreads();

    int run = wsums[wid] + (x - sum);
#pragma unroll
    for (int i = 0; i < CHUNK; i++) {
        int idx = base + i;
        if (idx < NN) {
            int c = g_cnt[idx];
            g_rowptr[idx] = run;
            g_cursor[idx] = run;
            run += c;
        }
    }
    if (tid == 0) g_rowptr[NN] = s_total;
}

__global__ void k_scatter(const int* __restrict__ ei32) {
    int e = blockIdx.x * blockDim.x + threadIdx.x;
    int is64 = g_is64;
    if (e < EE) {
        int d = ld_edge(ei32, EE + e, is64);
        int s = ld_edge(ei32, e, is64);
        int pos = atomicAdd(&g_cursor[d], 1);
        g_srcs[pos] = s;
    }
}

// ---------------- tf32 tensor-core GEMM (64x128 tile, cp.async 2-stage) ----------------
__device__ __forceinline__ unsigned tf32cvt(float f) {
    unsigned r;
    asm("cvt.rna.tf32.f32 %0, %1;" : "=r"(r) : "f"(f));
    return r;
}

__device__ __forceinline__ void cpasync16(unsigned dst_smem, const void* src, int sz) {
    asm volatile("cp.async.ca.shared.global [%0], [%1], 16, %2;"
                 :: "r"(dst_smem), "l"(src), "r"(sz));
}

__global__ __launch_bounds__(256) void k_gemm(
    const float* __restrict__ x, int x_from_h1,
    const float* __restrict__ W0, const float* __restrict__ b0,
    const float* __restrict__ W1, const float* __restrict__ b1)
{
    __shared__ float xs[2][64 * 32];    // swizzled A tiles (64 rows x 32 k)
    __shared__ float ws[2][32 * 136];   // padded-stride W chunks

    const float* xx = x_from_h1 ? g_h1 : x;
    const float* W  = blockIdx.y ? W1 : W0;
    const float* bb = blockIdx.y ? b1 : b0;
    float* out      = blockIdx.y ? g_xr : g_xl;

    const int row0 = blockIdx.x * 64;
    const int tid = threadIdx.x;
    const int wid = tid >> 5;
    const int lane = tid & 31;
    const int g = lane >> 2;
    const int t = lane & 3;

    const int mwarp = wid & 3;    // 0..3 -> 16 rows each
    const int nwarp = wid >> 2;   // 0..1 -> 64 cols each

    float acc[8][4];
#pragma unroll
    for (int nt = 0; nt < 8; nt++)
#pragma unroll
        for (int c = 0; c < 4; c++) acc[nt][c] = 0.f;

    auto load_chunk = [&](int kc, int buf) {
#pragma unroll
        for (int it = 0; it < 2; it++) {
            int idx = tid + it * 256;      // 0..511
            int m = idx >> 3;              // 0..63
            int kq = idx & 7;
            int gr = row0 + m;
            unsigned dst = (unsigned)__cvta_generic_to_shared(
                &xs[buf][m * 32 + (((kq + m) & 7) << 2)]);
            const float* src = &xx[(size_t)(gr < NN ? gr : 0) * 128 + kc + kq * 4];
            cpasync16(dst, src, gr < NN ? 16 : 0);
        }
#pragma unroll
        for (int it = 0; it < 4; it++) {
            int idx = tid + it * 256;
            int k = idx >> 5;
            int nq = idx & 31;
            unsigned dst = (unsigned)__cvta_generic_to_shared(&ws[buf][k * 136 + nq * 4]);
            cpasync16(dst, &W[(kc + k) * 128 + nq * 4], 16);
        }
        asm volatile("cp.async.commit_group;");
    };

    load_chunk(0, 0);

#pragma unroll
    for (int c = 0; c < 4; c++) {
        int buf = c & 1;
        if (c < 3) {
            load_chunk((c + 1) * 32, buf ^ 1);
            asm volatile("cp.async.wait_group 1;");
        } else {
            asm volatile("cp.async.wait_group 0;");
        }
        __syncthreads();

        const float* xsb = xs[buf];
        const float* wsb = ws[buf];
#pragma unroll
        for (int k8 = 0; k8 < 4; k8++) {
            int kb = k8 * 8;
            unsigned af[4];
            {
                int m0 = mwarp * 16 + g;
                int m1 = m0 + 8;
                int klo = kb + t, khi = kb + t + 4;
                af[0] = tf32cvt(xsb[m0 * 32 + ((((klo >> 2) + m0) & 7) << 2) + (klo & 3)]);
                af[1] = tf32cvt(xsb[m1 * 32 + ((((klo >> 2) + m1) & 7) << 2) + (klo & 3)]);
                af[2] = tf32cvt(xsb[m0 * 32 + ((((khi >> 2) + m0) & 7) << 2) + (khi & 3)]);
                af[3] = tf32cvt(xsb[m1 * 32 + ((((khi >> 2) + m1) & 7) << 2) + (khi & 3)]);
            }
            unsigned bf[8][2];
#pragma unroll
            for (int nt = 0; nt < 8; nt++) {
                int n = nwarp * 64 + nt * 8 + g;
                bf[nt][0] = tf32cvt(wsb[(kb + t) * 136 + n]);
                bf[nt][1] = tf32cvt(wsb[(kb + t + 4) * 136 + n]);
            }
#pragma unroll
            for (int nt = 0; nt < 8; nt++) {
                asm volatile(
                    "mma.sync.aligned.m16n8k8.row.col.f32.tf32.tf32.f32 "
                    "{%0,%1,%2,%3}, {%4,%5,%6,%7}, {%8,%9}, {%0,%1,%2,%3};"
                    : "+f"(acc[nt][0]), "+f"(acc[nt][1]),
                      "+f"(acc[nt][2]), "+f"(acc[nt][3])
                    : "r"(af[0]), "r"(af[1]), "r"(af[2]), "r"(af[3]),
                      "r"(bf[nt][0]), "r"(bf[nt][1]));
            }
        }
        __syncthreads();
    }

#pragma unroll
    for (int nt = 0; nt < 8; nt++) {
        int col = nwarp * 64 + nt * 8 + 2 * t;
        float bx = bb[col], by = bb[col + 1];
        int r0 = row0 + mwarp * 16 + g;
        int r1 = r0 + 8;
        if (r0 < NN) {
            float2 v = make_float2(acc[nt][0] + bx, acc[nt][1] + by);
            *(float2*)&out[r0 * 128 + col] = v;
        }
        if (r1 < NN) {
            float2 v = make_float2(acc[nt][2] + bx, acc[nt][3] + by);
            *(float2*)&out[r1 * 128 + col] = v;
        }
    }
}

// ---------------- fused attention + aggregation (two 16-lane edge streams) ----------------
// One warp per dst node. Half-warp h processes edges beg+h, beg+h+2, ... as an
// independent rolling-prefetch stream. Each lane owns 8 dims.
// IN-LOOP shuffles use the HALF-WARP mask (halves may run different trip
// counts for odd degree); halves reconverge via __syncwarp before combine.
__global__ __launch_bounds__(256) void k_aggregate(
    const float* __restrict__ att, const float* __restrict__ bias,
    float* __restrict__ out, int out_to_h1)
{
    int gw = (blockIdx.x * blockDim.x + threadIdx.x) >> 5;
    int lane = threadIdx.x & 31;
    if (gw >= NN) return;

    int half = lane >> 4;     // 0 or 1: edge stream
    int hl = lane & 15;       // lane within half: owns dims [hl*8, hl*8+8)
    unsigned hmask = 0xFFFFu << (half * 16);

    float* o = out_to_h1 ? g_h1 : out;

    int beg = g_rowptr[gw];
    int end = g_rowptr[gw + 1];

    const float* xrp = &g_xr[(size_t)gw * 128 + hl * 8];
    float4 xr0 = *(const float4*)&xrp[0];
    float4 xr1 = *(const float4*)&xrp[4];
    float4 at0 = *(const float4*)&att[hl * 8 + 0];
    float4 at1 = *(const float4*)&att[hl * 8 + 4];

    float4 ac0 = make_float4(0.f, 0.f, 0.f, 0.f);
    float4 ac1 = make_float4(0.f, 0.f, 0.f, 0.f);
    float wsum = 0.f;

    int j0 = beg + half;
    int sA = (j0 < end) ? g_srcs[j0] : 0;
    for (int j = j0; j < end; j += 2) {
        int s = sA;
        if (j + 2 < end) sA = g_srcs[j + 2];
        const float* xp = &g_xl[(size_t)s * 128 + hl * 8];
        float4 xv0 = *(const float4*)&xp[0];
        float4 xv1 = *(const float4*)&xp[4];

        float z, part = 0.f;
        z = xv0.x + xr0.x; z = z > 0.f ? z : SLOPE * z; part += z * at0.x;
        z = xv0.y + xr0.y; z = z > 0.f ? z : SLOPE * z; part += z * at0.y;
        z = xv0.z + xr0.z; z = z > 0.f ? z : SLOPE * z; part += z * at0.z;
        z = xv0.w + xr0.w; z = z > 0.f ? z : SLOPE * z; part += z * at0.w;
        z = xv1.x + xr1.x; z = z > 0.f ? z : SLOPE * z; part += z * at1.x;
        z = xv1.y + xr1.y; z = z > 0.f ? z : SLOPE * z; part += z * at1.y;
        z = xv1.z + xr1.z; z = z > 0.f ? z : SLOPE * z; part += z * at1.z;
        z = xv1.w + xr1.w; z = z > 0.f ? z : SLOPE * z; part += z * at1.w;

        // reduce within 16-lane half; half-warp mask (trip counts may differ)
        part += __shfl_xor_sync(hmask, part, 8);
        part += __shfl_xor_sync(hmask, part, 4);
        part += __shfl_xor_sync(hmask, part, 2);
        part += __shfl_xor_sync(hmask, part, 1);

        float w = __expf(part);
        ac0.x += w * xv0.x; ac0.y += w * xv0.y; ac0.z += w * xv0.z; ac0.w += w * xv0.w;
        ac1.x += w * xv1.x; ac1.y += w * xv1.y; ac1.z += w * xv1.z; ac1.w += w * xv1.w;
        wsum += w;
    }

    __syncwarp(0xffffffffu);   // reconverge halves before cross-half combine

    ac0.x += __shfl_xor_sync(0xffffffffu, ac0.x, 16);
    ac0.y += __shfl_xor_sync(0xffffffffu, ac0.y, 16);
    ac0.z += __shfl_xor_sync(0xffffffffu, ac0.z, 16);
    ac0.w += __shfl_xor_sync(0xffffffffu, ac0.w, 16);
    ac1.x += __shfl_xor_sync(0xffffffffu, ac1.x, 16);
    ac1.y += __shfl_xor_sync(0xffffffffu, ac1.y, 16);
    ac1.z += __shfl_xor_sync(0xffffffffu, ac1.z, 16);
    ac1.w += __shfl_xor_sync(0xffffffffu, ac1.w, 16);
    wsum  += __shfl_xor_sync(0xffffffffu, wsum, 16);

    if (half == 0) {
        float inv = 1.f / fmaxf(wsum, 1e-16f);
        float4 b0 = *(const float4*)&bias[hl * 8 + 0];
        float4 b1 = *(const float4*)&bias[hl * 8 + 4];
        float* op = &o[(size_t)gw * 128 + hl * 8];
        float4 r0, r1;
        r0.x = fmaxf(ac0.x * inv + b0.x, 0.f);
        r0.y = fmaxf(ac0.y * inv + b0.y, 0.f);
        r0.z = fmaxf(ac0.z * inv + b0.z, 0.f);
        r0.w = fmaxf(ac0.w * inv + b0.w, 0.f);
        r1.x = fmaxf(ac1.x * inv + b1.x, 0.f);
        r1.y = fmaxf(ac1.y * inv + b1.y, 0.f);
        r1.z = fmaxf(ac1.z * inv + b1.z, 0.f);
        r1.w = fmaxf(ac1.w * inv + b1.w, 0.f);
        *(float4*)&op[0] = r0;
        *(float4*)&op[4] = r1;
    }
}

// ---------------- launch ----------------
extern "C" void kernel_launch(void* const* d_in, const int* in_sizes, int n_in,
                              void* d_out, int out_size) {
    const float* x0    = (const float*)d_in[0];
    const int*   ei32  = (const int*)d_in[1];
    const float* Wl1   = (const float*)d_in[2];
    const float* bl1   = (const float*)d_in[3];
    const float* Wr1   = (const float*)d_in[4];
    const float* br1   = (const float*)d_in[5];
    const float* att1  = (const float*)d_in[6];
    const float* bias1 = (const float*)d_in[7];
    const float* Wl2   = (const float*)d_in[8];
    const float* bl2   = (const float*)d_in[9];
    const float* Wr2   = (const float*)d_in[10];
    const float* br2   = (const float*)d_in[11];
    const float* att2  = (const float*)d_in[12];
    const float* bias2 = (const float*)d_in[13];
    float* out = (float*)d_out;

    dim3 ggrid((NN + 63) / 64, 2);

    // CSR build + layer-1 gemm interleaved; gemm1 at profiled slot (index 3).
    k_zero_detect<<<(NN + 255) / 256, 256>>>(ei32);
    k_hist<<<(EE + 255) / 256, 256>>>(ei32);
    k_scan<<<1, 1024>>>();
    k_gemm<<<ggrid, 256>>>(x0, 0, Wl1, bl1, Wr1, br1);
    k_scatter<<<(EE + 255) / 256, 256>>>(ei32);

    k_aggregate<<<(NN * 32 + 255) / 256, 256>>>(att1, bias1, out, 1);

    k_gemm<<<ggrid, 256>>>(x0, 1, Wl2, bl2, Wr2, br2);
    k_aggregate<<<(NN * 32 + 255) / 256, 256>>>(att2, bias2, out, 0);
}